// round 13
// baseline (speedup 1.0000x reference)
#include <cuda_runtime.h>

#define NCOLS  8192
#define NWIN   513
#define NT     256
#define KPT    32

#define TLO (-1.31f)
#define THI ( 1.31f)
#define FINF  __int_as_float(0x7f800000)
#define FNINF __int_as_float(0xff800000)

__device__ __forceinline__ unsigned f2key(float x) {
    unsigned u = __float_as_uint(x);
    return (u & 0x80000000u) ? ~u : (u | 0x80000000u);
}
__device__ __forceinline__ float key2f(unsigned k) {
    unsigned u = (k & 0x80000000u) ? (k ^ 0x80000000u) : ~k;
    return __uint_as_float(u);
}

__device__ __forceinline__ void casf(float& a, float& b, bool up) {
    float lo = up ? fminf(a, b) : fmaxf(a, b);
    float hi = up ? fmaxf(a, b) : fminf(a, b);
    a = lo; b = hi;
}

__device__ __forceinline__ void sort8f(float v[8], bool up) {
    casf(v[0], v[4], up); casf(v[1], v[5], up); casf(v[2], v[6], up); casf(v[3], v[7], up);
    casf(v[0], v[2], up); casf(v[1], v[3], up); casf(v[4], v[6], up); casf(v[5], v[7], up);
    casf(v[0], v[1], up); casf(v[2], v[3], up); casf(v[4], v[5], up); casf(v[6], v[7], up);
}

// BRANCHLESS predication (ternary, not if — R5 proof).
__device__ __forceinline__ void shfl_pass(float v[8], int delta, bool up, int ts) {
    bool keepmin = (up == ((ts & delta) == 0));
    #pragma unroll
    for (int e = 0; e < 8; ++e) {
        float o = __shfl_xor_sync(0xffffffffu, v[e], delta);
        v[e] = keepmin ? fminf(v[e], o) : fmaxf(v[e], o);
    }
}

// delta >= 32: keepmin warp-uniform, branch free; 1 FMNMX per element.
__device__ __forceinline__ void smem_pass(float v[8], int delta, bool up,
                                          int t, int ts, float* scratch) {
    __syncthreads();
    #pragma unroll
    for (int e = 0; e < 8; ++e) scratch[t * 8 + e] = v[e];
    __syncthreads();
    bool keepmin = (up == ((ts & delta) == 0));
    int pt = t ^ delta;
    if (keepmin) {
        #pragma unroll
        for (int e = 0; e < 8; ++e) v[e] = fminf(v[e], scratch[pt * 8 + e]);
    } else {
        #pragma unroll
        for (int e = 0; e < 8; ++e) v[e] = fmaxf(v[e], scratch[pt * 8 + e]);
    }
}

// ---- exact fallback helpers (f2key domain; block-uniform; cold) ----
__device__ unsigned block_count(const float4* x4, unsigned K, bool ge,
                                unsigned* s_red, int tid) {
    if (tid == 0) *s_red = 0;
    __syncthreads();
    unsigned c = 0;
    for (int i = tid; i < NCOLS / 4; i += NT) {
        float4 w = x4[i];
        unsigned k0 = f2key(w.x), k1 = f2key(w.y), k2 = f2key(w.z), k3 = f2key(w.w);
        if (ge) c += (k0 >= K) + (k1 >= K) + (k2 >= K) + (k3 >= K);
        else    c += (k0 <= K) + (k1 <= K) + (k2 <= K) + (k3 <= K);
    }
    #pragma unroll
    for (int off = 16; off; off >>= 1) c += __shfl_down_sync(0xffffffffu, c, off);
    if ((tid & 31) == 0) atomicAdd(s_red, c);
    __syncthreads();
    unsigned r = *s_red;
    __syncthreads();
    return r;
}

// gathers as FLOATS (key2f applied); side 0: key<T, side 1: key>T
__device__ unsigned gather_side(const float4* x4, unsigned T, int side,
                                float* seg, unsigned* s_c, int tid) {
    if (tid == 0) *s_c = 0;
    __syncthreads();
    const int lane = tid & 31;
    for (int i = tid; i < NCOLS / 4; i += NT) {
        float4 w = x4[i];
        unsigned kk[4] = { f2key(w.x), f2key(w.y), f2key(w.z), f2key(w.w) };
        #pragma unroll
        for (int q = 0; q < 4; ++q) {
            bool take = side ? (kk[q] > T) : (kk[q] < T);
            unsigned m = __ballot_sync(0xffffffffu, take);
            unsigned base = 0;
            if (lane == 0 && m) base = atomicAdd(s_c, (unsigned)__popc(m));
            base = __shfl_sync(0xffffffffu, base, 0);
            if (take) {
                unsigned p = base + __popc(m & ((1u << lane) - 1u));
                if (p < 1024) seg[p] = key2f(kk[q]);
            }
        }
    }
    __syncthreads();
    unsigned r = *s_c;
    __syncthreads();
    return r;
}

__global__ __launch_bounds__(NT, 6)
void recall_window_kernel(const float* __restrict__ x,
                          float* __restrict__ out, int rows)
{
    __shared__ float    scratch[2048];     // two 1024-float sort segments
    __shared__ unsigned s_cnt[2];          // lo / hi append counters
    __shared__ unsigned s_c;               // fallback counter
    __shared__ unsigned long long s_best;

    const int t    = threadIdx.x;
    const int lane = t & 31;
    const int ts   = t & 127;
    const int row  = blockIdx.x;
    const float4* x4 = reinterpret_cast<const float4*>(x + (size_t)row * NCOLS);
    const unsigned lmask = (1u << lane) - 1u;

    if (t == 0) { s_cnt[0] = 0; s_cnt[1] = 0; s_best = ~0ull; }
    __syncthreads();

    // ---- single-pass warp-aggregated gather: one leader ATOMS per warp per
    // 32-elem group per side (~512 spread atomics/row total — no R12-style
    // same-address serialization). In-warp rank from ballot popc keeps writes
    // compact; within-segment order is nondeterministic but the sort
    // canonicalizes it, so outputs stay deterministic.
    #pragma unroll
    for (int e4 = 0; e4 < KPT / 4; ++e4) {
        float4 w = x4[e4 * NT + t];
        float fa[4] = { w.x, w.y, w.z, w.w };
        #pragma unroll
        for (int q = 0; q < 4; ++q) {
            float f  = fa[q];
            bool lo  = (f < TLO);
            bool hi  = (f > THI);
            unsigned mlo = __ballot_sync(0xffffffffu, lo);
            unsigned mhi = __ballot_sync(0xffffffffu, hi);
            unsigned blo = 0, bhi = 0;
            if (lane == 0) {
                if (mlo) blo = atomicAdd(&s_cnt[0], (unsigned)__popc(mlo));
                if (mhi) bhi = atomicAdd(&s_cnt[1], (unsigned)__popc(mhi));
            }
            blo = __shfl_sync(0xffffffffu, blo, 0);
            bhi = __shfl_sync(0xffffffffu, bhi, 0);
            if (lo) {
                unsigned p = blo + (unsigned)__popc(mlo & lmask);
                if (p < 1024u) scratch[p] = f;
            } else if (hi) {
                unsigned p = bhi + (unsigned)__popc(mhi & lmask);
                if (p < 1024u) scratch[1024u + p] = f;
            }
        }
    }
    __syncthreads();

    unsigned totlo = s_cnt[0], tothi = s_cnt[1];
    const bool ok_lo = (totlo >= 513u && totlo <= 1024u);
    const bool ok_hi = (tothi >= 513u && tothi <= 1024u);

    unsigned c0 = totlo, c1 = tothi;
    if (!ok_lo) {                                   // exact fallback (cold)
        unsigned Kcut;
        if (block_count(x4, 0u, false, &s_c, t) >= 513u) {
            Kcut = 0u;
        } else {
            unsigned X = 0;
            for (int b = 31; b >= 0; --b) {
                unsigned X2 = X | (1u << b);
                if (block_count(x4, X2, false, &s_c, t) < 513u) X = X2;
            }
            Kcut = X + 1u;                          // exact s[512] key
        }
        c0 = gather_side(x4, Kcut, 0, scratch, &s_c, t);
        float fK = key2f(Kcut);
        for (int i = (int)c0 + t; i < 513; i += NT) scratch[i] = fK;
        c0 = 513u;
    }
    if (!ok_hi) {
        unsigned Y = 0;
        for (int b = 31; b >= 0; --b) {
            unsigned Y2 = Y | (1u << b);
            if (block_count(x4, Y2, true, &s_c, t) >= 513u) Y = Y2;   // exact s[7679]
        }
        c1 = gather_side(x4, Y, 1, scratch + 1024, &s_c, t);
        float fY = key2f(Y);
        for (int i = (int)c1 + t; i < 513; i += NT) scratch[1024 + i] = fY;
        c1 = 513u;
    }
    // pads: lo-end with +INF, hi-front with -INF
    for (int i = (int)c0 + t; i < 1024; i += NT) scratch[i]        = FINF;
    for (int i = (int)c1 + t; i < 1024; i += NT) scratch[1024 + i] = FNINF;
    __syncthreads();

    // ---- register-blocked float bitonic, two independent 1024 sorts ----
    float v[8];
    #pragma unroll
    for (int e = 0; e < 8; ++e) v[e] = scratch[t * 8 + e];

    casf(v[0], v[1], true);  casf(v[2], v[3], false);
    casf(v[4], v[5], true);  casf(v[6], v[7], false);
    casf(v[0], v[2], true);  casf(v[1], v[3], true);
    casf(v[4], v[6], false); casf(v[5], v[7], false);
    casf(v[0], v[1], true);  casf(v[2], v[3], true);
    casf(v[4], v[5], false); casf(v[6], v[7], false);
    sort8f(v, (ts & 1) == 0);

    #pragma unroll
    for (int kk = 16; kk <= 1024; kk <<= 1) {
        bool up = ((ts & (kk >> 3)) == 0);
        #pragma unroll
        for (int j = kk >> 1; j >= 8; j >>= 1) {
            int delta = j >> 3;
            if (delta >= 32) smem_pass(v, delta, up, t, ts, scratch);
            else             shfl_pass(v, delta, up, ts);
        }
        sort8f(v, up);
    }

    __syncthreads();
    #pragma unroll
    for (int e = 0; e < 8; ++e) scratch[t * 8 + e] = v[e];
    __syncthreads();
    // lo sorted: s[i] = scratch[i], i in [0,512]
    // hi sorted asc (-INF pads first): s[7679+j] = scratch[1024 + 511 + j]

    // ---- lengths + first-index argmin ----
    unsigned long long best = ~0ull;
    for (int i = t; i < NWIN; i += NT) {
        float len = scratch[1024 + 511 + i] - scratch[i];   // >= 0
        unsigned long long p =
            ((unsigned long long)__float_as_uint(len) << 32) | (unsigned)i;
        best = (p < best) ? p : best;
    }
    #pragma unroll
    for (int off = 16; off; off >>= 1) {
        unsigned long long o = __shfl_down_sync(0xffffffffu, best, off);
        best = (o < best) ? o : best;
    }
    if (lane == 0) atomicMin(&s_best, best);
    __syncthreads();

    if (t == 0) {
        int idx = (int)(unsigned)(s_best & 0xffffffffu);
        out[row]        = scratch[idx];
        out[rows + row] = scratch[1024 + 511 + idx];
    }
}

extern "C" void kernel_launch(void* const* d_in, const int* in_sizes, int n_in,
                              void* d_out, int out_size) {
    const float* x = (const float*)d_in[0];
    float* out = (float*)d_out;
    int rows = in_sizes[0] / NCOLS;   // 4096
    recall_window_kernel<<<rows, NT>>>(x, out, rows);
}

// round 14
// speedup vs baseline: 1.5944x; 1.5944x over previous
#include <cuda_runtime.h>

#define NCOLS  8192
#define NWIN   513
#define NT     256
#define KPT    32

#define TLO (-1.31f)
#define THI ( 1.31f)
#define FINF  __int_as_float(0x7f800000)
#define FNINF __int_as_float(0xff800000)

__device__ __forceinline__ unsigned f2key(float x) {
    unsigned u = __float_as_uint(x);
    return (u & 0x80000000u) ? ~u : (u | 0x80000000u);
}
__device__ __forceinline__ float key2f(unsigned k) {
    unsigned u = (k & 0x80000000u) ? (k ^ 0x80000000u) : ~k;
    return __uint_as_float(u);
}

__device__ __forceinline__ void casf(float& a, float& b, bool up) {
    float lo = up ? fminf(a, b) : fmaxf(a, b);
    float hi = up ? fmaxf(a, b) : fminf(a, b);
    a = lo; b = hi;
}

// bitonic-merge step for 8 regs (input bitonic per stage invariant)
__device__ __forceinline__ void sort8f(float v[8], bool up) {
    casf(v[0], v[4], up); casf(v[1], v[5], up); casf(v[2], v[6], up); casf(v[3], v[7], up);
    casf(v[0], v[2], up); casf(v[1], v[3], up); casf(v[4], v[6], up); casf(v[5], v[7], up);
    casf(v[0], v[1], up); casf(v[2], v[3], up); casf(v[4], v[5], up); casf(v[6], v[7], up);
}

// Batcher odd-even 8-sort: 19 comparators (vs 24 for the bitonic build).
// Direction-parameterized: up=false sorts descending.
__device__ __forceinline__ void batcher8f(float v[8], bool up) {
    casf(v[0], v[1], up); casf(v[2], v[3], up); casf(v[4], v[5], up); casf(v[6], v[7], up);
    casf(v[0], v[2], up); casf(v[1], v[3], up); casf(v[4], v[6], up); casf(v[5], v[7], up);
    casf(v[1], v[2], up); casf(v[5], v[6], up);
    casf(v[0], v[4], up); casf(v[1], v[5], up); casf(v[2], v[6], up); casf(v[3], v[7], up);
    casf(v[2], v[4], up); casf(v[3], v[5], up);
    casf(v[1], v[2], up); casf(v[3], v[4], up); casf(v[5], v[6], up);
}

// BRANCHLESS predication (ternary, not if — R5 proof).
__device__ __forceinline__ void shfl_pass(float v[8], int delta, bool up, int ts) {
    bool keepmin = (up == ((ts & delta) == 0));
    #pragma unroll
    for (int e = 0; e < 8; ++e) {
        float o = __shfl_xor_sync(0xffffffffu, v[e], delta);
        v[e] = keepmin ? fminf(v[e], o) : fmaxf(v[e], o);
    }
}

// delta >= 32: keepmin warp-uniform, branch free; 1 FMNMX per element.
__device__ __forceinline__ void smem_pass(float v[8], int delta, bool up,
                                          int t, int ts, float* scratch) {
    __syncthreads();
    #pragma unroll
    for (int e = 0; e < 8; ++e) scratch[t * 8 + e] = v[e];
    __syncthreads();
    bool keepmin = (up == ((ts & delta) == 0));
    int pt = t ^ delta;
    if (keepmin) {
        #pragma unroll
        for (int e = 0; e < 8; ++e) v[e] = fminf(v[e], scratch[pt * 8 + e]);
    } else {
        #pragma unroll
        for (int e = 0; e < 8; ++e) v[e] = fmaxf(v[e], scratch[pt * 8 + e]);
    }
}

// ---- exact fallback helpers (f2key domain; block-uniform; cold) ----
__device__ unsigned block_count(const float4* x4, unsigned K, bool ge,
                                unsigned* s_red, int tid) {
    if (tid == 0) *s_red = 0;
    __syncthreads();
    unsigned c = 0;
    for (int i = tid; i < NCOLS / 4; i += NT) {
        float4 w = x4[i];
        unsigned k0 = f2key(w.x), k1 = f2key(w.y), k2 = f2key(w.z), k3 = f2key(w.w);
        if (ge) c += (k0 >= K) + (k1 >= K) + (k2 >= K) + (k3 >= K);
        else    c += (k0 <= K) + (k1 <= K) + (k2 <= K) + (k3 <= K);
    }
    #pragma unroll
    for (int off = 16; off; off >>= 1) c += __shfl_down_sync(0xffffffffu, c, off);
    if ((tid & 31) == 0) atomicAdd(s_red, c);
    __syncthreads();
    unsigned r = *s_red;
    __syncthreads();
    return r;
}

// gathers as FLOATS (key2f applied); side 0: key<T, side 1: key>T
__device__ unsigned gather_side(const float4* x4, unsigned T, int side,
                                float* seg, unsigned* s_c, int tid) {
    if (tid == 0) *s_c = 0;
    __syncthreads();
    const int lane = tid & 31;
    for (int i = tid; i < NCOLS / 4; i += NT) {
        float4 w = x4[i];
        unsigned kk[4] = { f2key(w.x), f2key(w.y), f2key(w.z), f2key(w.w) };
        #pragma unroll
        for (int q = 0; q < 4; ++q) {
            bool take = side ? (kk[q] > T) : (kk[q] < T);
            unsigned m = __ballot_sync(0xffffffffu, take);
            unsigned base = 0;
            if (lane == 0 && m) base = atomicAdd(s_c, (unsigned)__popc(m));
            base = __shfl_sync(0xffffffffu, base, 0);
            if (take) {
                unsigned p = base + __popc(m & ((1u << lane) - 1u));
                if (p < 1024) seg[p] = key2f(kk[q]);
            }
        }
    }
    __syncthreads();
    unsigned r = *s_c;
    __syncthreads();
    return r;
}

__global__ __launch_bounds__(NT, 7)
void recall_window_kernel(const float* __restrict__ x,
                          float* __restrict__ out, int rows)
{
    __shared__ float    scratch[2048];     // two 1024-float sort segments
    __shared__ unsigned wsum[8];
    __shared__ unsigned s_c;
    __shared__ unsigned long long s_best;

    const int t    = threadIdx.x;
    const int lane = t & 31;
    const int wid  = t >> 5;
    const int ts   = t & 127;
    const int row  = blockIdx.x;
    const float4* x4 = reinterpret_cast<const float4*>(x + (size_t)row * NCOLS);

    // ---- phase 1: load + count tail takes ----
    unsigned clo = 0, chi = 0;
    #pragma unroll
    for (int e4 = 0; e4 < KPT / 4; ++e4) {
        float4 w = x4[e4 * NT + t];
        clo += (w.x < TLO) + (w.y < TLO) + (w.z < TLO) + (w.w < TLO);
        chi += (w.x > THI) + (w.y > THI) + (w.z > THI) + (w.w > THI);
    }

    // ---- phase 2: block exclusive scan of packed (clo | chi<<16) ----
    unsigned packed = clo | (chi << 16);
    unsigned incl = packed;
    #pragma unroll
    for (int off = 1; off < 32; off <<= 1) {
        unsigned v = __shfl_up_sync(0xffffffffu, incl, off);
        if (lane >= off) incl += v;
    }
    if (lane == 31) wsum[wid] = incl;
    __syncthreads();
    unsigned wbase = 0, tot = 0;
    #pragma unroll
    for (int w = 0; w < 8; ++w) {
        unsigned s = wsum[w];
        wbase += (w < wid) ? s : 0u;
        tot   += s;
    }
    unsigned excl   = wbase + incl - packed;
    unsigned baselo = excl & 0xFFFFu, basehi = excl >> 16;
    unsigned totlo  = tot  & 0xFFFFu, tothi  = tot  >> 16;

    const bool ok_lo = (totlo >= 513u && totlo <= 1024u);
    const bool ok_hi = (tothi >= 513u && tothi <= 1024u);

    // ---- phase 3: re-read row (cache-hot), scatter floats directly ----
    if (ok_lo && ok_hi) {
        unsigned plo = baselo, phi = basehi;
        #pragma unroll
        for (int e4 = 0; e4 < KPT / 4; ++e4) {
            float4 w = x4[e4 * NT + t];
            float fa[4] = { w.x, w.y, w.z, w.w };
            #pragma unroll
            for (int q = 0; q < 4; ++q) {
                float f = fa[q];
                if (f < TLO)      scratch[plo++] = f;
                else if (f > THI) scratch[1024 + phi++] = f;
            }
        }
    }
    __syncthreads();

    unsigned c0 = totlo, c1 = tothi;
    if (!ok_lo) {                                   // exact fallback (cold)
        unsigned Kcut;
        if (block_count(x4, 0u, false, &s_c, t) >= 513u) {
            Kcut = 0u;
        } else {
            unsigned X = 0;
            for (int b = 31; b >= 0; --b) {
                unsigned X2 = X | (1u << b);
                if (block_count(x4, X2, false, &s_c, t) < 513u) X = X2;
            }
            Kcut = X + 1u;                          // exact s[512] key
        }
        c0 = gather_side(x4, Kcut, 0, scratch, &s_c, t);
        float fK = key2f(Kcut);
        for (int i = (int)c0 + t; i < 513; i += NT) scratch[i] = fK;
        c0 = 513u;
    }
    if (!ok_hi) {
        unsigned Y = 0;
        for (int b = 31; b >= 0; --b) {
            unsigned Y2 = Y | (1u << b);
            if (block_count(x4, Y2, true, &s_c, t) >= 513u) Y = Y2;   // exact s[7679]
        }
        c1 = gather_side(x4, Y, 1, scratch + 1024, &s_c, t);
        float fY = key2f(Y);
        for (int i = (int)c1 + t; i < 513; i += NT) scratch[1024 + i] = fY;
        c1 = 513u;
    }
    // pads: lo-end with +INF, hi-front with -INF
    for (int i = (int)c0 + t; i < 1024; i += NT) scratch[i]        = FINF;
    for (int i = (int)c1 + t; i < 1024; i += NT) scratch[1024 + i] = FNINF;
    if (t == 0) s_best = ~0ull;
    __syncthreads();

    // ---- phase 4: register-blocked float bitonic, two independent 1024 sorts ----
    float v[8];
    #pragma unroll
    for (int e = 0; e < 8; ++e) v[e] = scratch[t * 8 + e];

    // sorted 8-runs, alternating direction (Batcher, 19 comparators)
    batcher8f(v, (ts & 1) == 0);

    #pragma unroll
    for (int kk = 16; kk <= 1024; kk <<= 1) {
        bool up = ((ts & (kk >> 3)) == 0);
        #pragma unroll
        for (int j = kk >> 1; j >= 8; j >>= 1) {
            int delta = j >> 3;
            if (delta >= 32) smem_pass(v, delta, up, t, ts, scratch);
            else             shfl_pass(v, delta, up, ts);
        }
        sort8f(v, up);
    }

    __syncthreads();
    #pragma unroll
    for (int e = 0; e < 8; ++e) scratch[t * 8 + e] = v[e];
    __syncthreads();
    // lo sorted: s[i] = scratch[i], i in [0,512]
    // hi sorted asc (-INF pads first): s[7679+j] = scratch[1024 + 511 + j]

    // ---- phase 5: lengths + first-index argmin ----
    unsigned long long best = ~0ull;
    for (int i = t; i < NWIN; i += NT) {
        float len = scratch[1024 + 511 + i] - scratch[i];   // >= 0
        unsigned long long p =
            ((unsigned long long)__float_as_uint(len) << 32) | (unsigned)i;
        best = (p < best) ? p : best;
    }
    #pragma unroll
    for (int off = 16; off; off >>= 1) {
        unsigned long long o = __shfl_down_sync(0xffffffffu, best, off);
        best = (o < best) ? o : best;
    }
    if (lane == 0) atomicMin(&s_best, best);
    __syncthreads();

    if (t == 0) {
        int idx = (int)(unsigned)(s_best & 0xffffffffu);
        out[row]        = scratch[idx];
        out[rows + row] = scratch[1024 + 511 + idx];
    }
}

extern "C" void kernel_launch(void* const* d_in, const int* in_sizes, int n_in,
                              void* d_out, int out_size) {
    const float* x = (const float*)d_in[0];
    float* out = (float*)d_out;
    int rows = in_sizes[0] / NCOLS;   // 4096
    recall_window_kernel<<<rows, NT>>>(x, out, rows);
}

// round 15
// speedup vs baseline: 1.7990x; 1.1283x over previous
#include <cuda_runtime.h>

#define NCOLS  8192
#define NWIN   513
#define NT     256
#define KPT    32

#define TLO (-1.31f)
#define THI ( 1.31f)
#define FINF  __int_as_float(0x7f800000)
#define FNINF __int_as_float(0xff800000)

__device__ __forceinline__ unsigned f2key(float x) {
    unsigned u = __float_as_uint(x);
    return (u & 0x80000000u) ? ~u : (u | 0x80000000u);
}
__device__ __forceinline__ float key2f(unsigned k) {
    unsigned u = (k & 0x80000000u) ? (k ^ 0x80000000u) : ~k;
    return __uint_as_float(u);
}

__device__ __forceinline__ void casf(float& a, float& b, bool up) {
    float lo = up ? fminf(a, b) : fmaxf(a, b);
    float hi = up ? fmaxf(a, b) : fminf(a, b);
    a = lo; b = hi;
}

// bitonic-merge step for 8 regs
__device__ __forceinline__ void sort8f(float v[8], bool up) {
    casf(v[0], v[4], up); casf(v[1], v[5], up); casf(v[2], v[6], up); casf(v[3], v[7], up);
    casf(v[0], v[2], up); casf(v[1], v[3], up); casf(v[4], v[6], up); casf(v[5], v[7], up);
    casf(v[0], v[1], up); casf(v[2], v[3], up); casf(v[4], v[5], up); casf(v[6], v[7], up);
}

// Batcher odd-even 8-sort: 19 comparators.
__device__ __forceinline__ void batcher8f(float v[8], bool up) {
    casf(v[0], v[1], up); casf(v[2], v[3], up); casf(v[4], v[5], up); casf(v[6], v[7], up);
    casf(v[0], v[2], up); casf(v[1], v[3], up); casf(v[4], v[6], up); casf(v[5], v[7], up);
    casf(v[1], v[2], up); casf(v[5], v[6], up);
    casf(v[0], v[4], up); casf(v[1], v[5], up); casf(v[2], v[6], up); casf(v[3], v[7], up);
    casf(v[2], v[4], up); casf(v[3], v[5], up);
    casf(v[1], v[2], up); casf(v[3], v[4], up); casf(v[5], v[6], up);
}

// BRANCHLESS predication (ternary, not if — R5 proof).
__device__ __forceinline__ void shfl_pass(float v[8], int delta, bool up, int ts) {
    bool keepmin = (up == ((ts & delta) == 0));
    #pragma unroll
    for (int e = 0; e < 8; ++e) {
        float o = __shfl_xor_sync(0xffffffffu, v[e], delta);
        v[e] = keepmin ? fminf(v[e], o) : fmaxf(v[e], o);
    }
}

// delta >= 32: keepmin warp-uniform, branch free.
__device__ __forceinline__ void smem_pass(float v[8], int delta, bool up,
                                          int t, int ts, float* scratch) {
    __syncthreads();
    #pragma unroll
    for (int e = 0; e < 8; ++e) scratch[t * 8 + e] = v[e];
    __syncthreads();
    bool keepmin = (up == ((ts & delta) == 0));
    int pt = t ^ delta;
    if (keepmin) {
        #pragma unroll
        for (int e = 0; e < 8; ++e) v[e] = fminf(v[e], scratch[pt * 8 + e]);
    } else {
        #pragma unroll
        for (int e = 0; e < 8; ++e) v[e] = fmaxf(v[e], scratch[pt * 8 + e]);
    }
}

// ---- exact fallback helpers (f2key domain; block-uniform; cold) ----
__device__ unsigned block_count(const float4* x4, unsigned K, bool ge,
                                unsigned* s_red, int tid) {
    if (tid == 0) *s_red = 0;
    __syncthreads();
    unsigned c = 0;
    for (int i = tid; i < NCOLS / 4; i += NT) {
        float4 w = x4[i];
        unsigned k0 = f2key(w.x), k1 = f2key(w.y), k2 = f2key(w.z), k3 = f2key(w.w);
        if (ge) c += (k0 >= K) + (k1 >= K) + (k2 >= K) + (k3 >= K);
        else    c += (k0 <= K) + (k1 <= K) + (k2 <= K) + (k3 <= K);
    }
    #pragma unroll
    for (int off = 16; off; off >>= 1) c += __shfl_down_sync(0xffffffffu, c, off);
    if ((tid & 31) == 0) atomicAdd(s_red, c);
    __syncthreads();
    unsigned r = *s_red;
    __syncthreads();
    return r;
}

__device__ unsigned gather_side(const float4* x4, unsigned T, int side,
                                float* seg, unsigned* s_c, int tid) {
    if (tid == 0) *s_c = 0;
    __syncthreads();
    const int lane = tid & 31;
    for (int i = tid; i < NCOLS / 4; i += NT) {
        float4 w = x4[i];
        unsigned kk[4] = { f2key(w.x), f2key(w.y), f2key(w.z), f2key(w.w) };
        #pragma unroll
        for (int q = 0; q < 4; ++q) {
            bool take = side ? (kk[q] > T) : (kk[q] < T);
            unsigned m = __ballot_sync(0xffffffffu, take);
            unsigned base = 0;
            if (lane == 0 && m) base = atomicAdd(s_c, (unsigned)__popc(m));
            base = __shfl_sync(0xffffffffu, base, 0);
            if (take) {
                unsigned p = base + __popc(m & ((1u << lane) - 1u));
                if (p < 1024) seg[p] = key2f(kk[q]);
            }
        }
    }
    __syncthreads();
    unsigned r = *s_c;
    __syncthreads();
    return r;
}

__global__ __launch_bounds__(NT, 6)
void recall_window_kernel(const float* __restrict__ x,
                          float* __restrict__ out, int rows)
{
    __shared__ float    scratch[2048];
    __shared__ unsigned wsum[8];
    __shared__ float    wred[8];
    __shared__ unsigned s_c;
    __shared__ unsigned long long s_best;

    const int t    = threadIdx.x;
    const int lane = t & 31;
    const int wid  = t >> 5;
    const int ts   = t & 127;
    const int row  = blockIdx.x;
    const float4* x4 = reinterpret_cast<const float4*>(x + (size_t)row * NCOLS);

    // ---- phase 1: load + count tail takes ----
    unsigned clo = 0, chi = 0;
    #pragma unroll
    for (int e4 = 0; e4 < KPT / 4; ++e4) {
        float4 w = x4[e4 * NT + t];
        clo += (w.x < TLO) + (w.y < TLO) + (w.z < TLO) + (w.w < TLO);
        chi += (w.x > THI) + (w.y > THI) + (w.z > THI) + (w.w > THI);
    }

    // ---- phase 2: block exclusive scan of packed (clo | chi<<16) ----
    unsigned packed = clo | (chi << 16);
    unsigned incl = packed;
    #pragma unroll
    for (int off = 1; off < 32; off <<= 1) {
        unsigned v = __shfl_up_sync(0xffffffffu, incl, off);
        if (lane >= off) incl += v;
    }
    if (lane == 31) wsum[wid] = incl;
    __syncthreads();
    unsigned wbase = 0, tot = 0;
    #pragma unroll
    for (int w = 0; w < 8; ++w) {
        unsigned s = wsum[w];
        wbase += (w < wid) ? s : 0u;
        tot   += s;
    }
    unsigned excl   = wbase + incl - packed;
    unsigned baselo = excl & 0xFFFFu, basehi = excl >> 16;
    unsigned totlo  = tot  & 0xFFFFu, tothi  = tot  >> 16;

    const bool ok_lo = (totlo >= 513u && totlo <= 1024u);
    const bool ok_hi = (tothi >= 513u && tothi <= 1024u);

    // ---- phase 3: re-read row (cache-hot), scatter floats directly ----
    if (ok_lo && ok_hi) {
        unsigned plo = baselo, phi = basehi;
        #pragma unroll
        for (int e4 = 0; e4 < KPT / 4; ++e4) {
            float4 w = x4[e4 * NT + t];
            float fa[4] = { w.x, w.y, w.z, w.w };
            #pragma unroll
            for (int q = 0; q < 4; ++q) {
                float f = fa[q];
                if (f < TLO)      scratch[plo++] = f;
                else if (f > THI) scratch[1024 + phi++] = f;
            }
        }
    }
    __syncthreads();

    unsigned c0 = totlo, c1 = tothi;
    if (!ok_lo) {                                   // exact fallback (cold)
        unsigned Kcut;
        if (block_count(x4, 0u, false, &s_c, t) >= 513u) {
            Kcut = 0u;
        } else {
            unsigned X = 0;
            for (int b = 31; b >= 0; --b) {
                unsigned X2 = X | (1u << b);
                if (block_count(x4, X2, false, &s_c, t) < 513u) X = X2;
            }
            Kcut = X + 1u;
        }
        c0 = gather_side(x4, Kcut, 0, scratch, &s_c, t);
        float fK = key2f(Kcut);
        for (int i = (int)c0 + t; i < 513; i += NT) scratch[i] = fK;
        c0 = 513u;
    }
    if (!ok_hi) {
        unsigned Y = 0;
        for (int b = 31; b >= 0; --b) {
            unsigned Y2 = Y | (1u << b);
            if (block_count(x4, Y2, true, &s_c, t) >= 513u) Y = Y2;
        }
        c1 = gather_side(x4, Y, 1, scratch + 1024, &s_c, t);
        float fY = key2f(Y);
        for (int i = (int)c1 + t; i < 513; i += NT) scratch[1024 + i] = fY;
        c1 = 513u;
    }
    for (int i = (int)c0 + t; i < 1024; i += NT) scratch[i]        = FINF;
    for (int i = (int)c1 + t; i < 1024; i += NT) scratch[1024 + i] = FNINF;
    if (t == 0) s_best = ~0ull;
    __syncthreads();

    // ---- phase 4: register-blocked bitonic, stages up to 512 ----
    float v[8];
    #pragma unroll
    for (int e = 0; e < 8; ++e) v[e] = scratch[t * 8 + e];

    batcher8f(v, (ts & 1) == 0);

    #pragma unroll
    for (int kk = 16; kk <= 512; kk <<= 1) {
        bool up = ((ts & (kk >> 3)) == 0);
        #pragma unroll
        for (int j = kk >> 1; j >= 8; j >>= 1) {
            int delta = j >> 3;
            if (delta >= 32) smem_pass(v, delta, up, t, ts, scratch);
            else             shfl_pass(v, delta, up, ts);
        }
        sort8f(v, up);
    }

    // ---- final merge stage kk=1024 (up = true), PRUNED:
    // lo needs [0..512]; hi needs [511..1023]. After the delta-64
    // separation, the unneeded half of each segment only contributes its
    // boundary extremum — compute it by reduction and skip its sort.
    smem_pass(v, 64, true, t, ts, scratch);       // separation (all threads)

    const bool need = (t < 128) ? (ts < 64) : (ts >= 64);   // warp-uniform

    float red = 0.0f;
    if (!need) {
        if (t < 128) {   // lo top half -> s[512] = min
            red = fminf(fminf(fminf(v[0], v[1]), fminf(v[2], v[3])),
                        fminf(fminf(v[4], v[5]), fminf(v[6], v[7])));
            #pragma unroll
            for (int off = 16; off; off >>= 1)
                red = fminf(red, __shfl_xor_sync(0xffffffffu, red, off));
        } else {         // hi bottom half -> s_hi[511] = max
            red = fmaxf(fmaxf(fmaxf(v[0], v[1]), fmaxf(v[2], v[3])),
                        fmaxf(fmaxf(v[4], v[5]), fmaxf(v[6], v[7])));
            #pragma unroll
            for (int off = 16; off; off >>= 1)
                red = fmaxf(red, __shfl_xor_sync(0xffffffffu, red, off));
        }
    }

    // delta-32 smem pass restricted to active halves (barriers by ALL)
    __syncthreads();
    if (need) {
        #pragma unroll
        for (int e = 0; e < 8; ++e) scratch[t * 8 + e] = v[e];
    }
    __syncthreads();
    if (need) {
        bool keepmin = ((ts & 32) == 0);          // warp-uniform
        int pt = t ^ 32;                          // partner also active
        if (keepmin) {
            #pragma unroll
            for (int e = 0; e < 8; ++e) v[e] = fminf(v[e], scratch[pt * 8 + e]);
        } else {
            #pragma unroll
            for (int e = 0; e < 8; ++e) v[e] = fmaxf(v[e], scratch[pt * 8 + e]);
        }
        shfl_pass(v, 16, true, ts);
        shfl_pass(v,  8, true, ts);
        shfl_pass(v,  4, true, ts);
        shfl_pass(v,  2, true, ts);
        shfl_pass(v,  1, true, ts);
        sort8f(v, true);
    }

    // writeback + boundary elements
    __syncthreads();
    #pragma unroll
    for (int e = 0; e < 8; ++e) scratch[t * 8 + e] = v[e];
    if (!need && lane == 0) wred[wid] = red;      // wids 2,3 (lo-top) / 4,5 (hi-bot)
    __syncthreads();
    if (t == 0) {
        scratch[512]  = fminf(wred[2], wred[3]);  // lo s[512]
        scratch[1535] = fmaxf(wred[4], wred[5]);  // hi s[511] (= 1024+511)
    }
    __syncthreads();
    // lo sorted: s[i] = scratch[i], i in [0,512]
    // hi: s[7679+j] = scratch[1024 + 511 + j], j in [0,512]

    // ---- phase 5: lengths + first-index argmin ----
    unsigned long long best = ~0ull;
    for (int i = t; i < NWIN; i += NT) {
        float len = scratch[1024 + 511 + i] - scratch[i];
        unsigned long long p =
            ((unsigned long long)__float_as_uint(len) << 32) | (unsigned)i;
        best = (p < best) ? p : best;
    }
    #pragma unroll
    for (int off = 16; off; off >>= 1) {
        unsigned long long o = __shfl_down_sync(0xffffffffu, best, off);
        best = (o < best) ? o : best;
    }
    if (lane == 0) atomicMin(&s_best, best);
    __syncthreads();

    if (t == 0) {
        int idx = (int)(unsigned)(s_best & 0xffffffffu);
        out[row]        = scratch[idx];
        out[rows + row] = scratch[1024 + 511 + idx];
    }
}

extern "C" void kernel_launch(void* const* d_in, const int* in_sizes, int n_in,
                              void* d_out, int out_size) {
    const float* x = (const float*)d_in[0];
    float* out = (float*)d_out;
    int rows = in_sizes[0] / NCOLS;   // 4096
    recall_window_kernel<<<rows, NT>>>(x, out, rows);
}